// round 4
// baseline (speedup 1.0000x reference)
#include <cuda_runtime.h>
#include <cuda_bf16.h>
#include <cstdint>

// ---------------------------------------------------------------------------
// DynamicModel hypernetwork:
//   MLP(16->256->512->19296, relu all) generates per-sample conv weights
//   conv0: 1->32 3x3 SAME ; conv1: 32->64 (mma.sync tf32, persistent) ; conv2: 64->1
//   B=16, H=W=256
// ---------------------------------------------------------------------------

static const int B = 16, H = 256, W = 256;
static const int TOTAL_W = 19296;
static const int OFF_W1 = 288;
static const int OFF_W2 = 18720;

// conv1 weight fragment layout (per batch): row = (s*4+kk)*4 + jl, 144 rows
// of 68 float2 (oc 0..63 + pad): f2[oc] = (w[jh=0], w[jh=1]) for col j=jh*4+jl
static const int WROW_F2 = 68;
static const int WT_PER_B = 144 * WROW_F2 * 2;   // 19584 floats

// Scratch
__device__ float g_h1[16 * 512];
__device__ float g_flat[16 * TOTAL_W];
__device__ float g_wt[16 * WT_PER_B];
// conv0 output: pair-interleaved planar, padded 258x258 with zero border.
// plane p = kk*4+jl (16 planes), value = float2(c0[kk*8+jl], c0[kk*8+4+jl])
__device__ float2 g_c0p[(size_t)16 * 16 * 258 * 258];
__device__ float g_c1[(size_t)16 * 64 * 256 * 256];      // planar [b][oc][y][x]

// ---------------- helpers ----------------
__device__ __forceinline__ float tf32r(float x) {
    unsigned u;
    asm("cvt.rna.tf32.f32 %0, %1;" : "=r"(u) : "f"(x));
    return __uint_as_float(u);
}
__device__ __forceinline__ uint32_t smem_u32(const void* p) {
    uint32_t a;
    asm("{ .reg .u64 t; cvta.to.shared.u64 t, %1; cvt.u32.u64 %0, t; }" : "=r"(a) : "l"(p));
    return a;
}

__device__ __forceinline__ void mma_tf32(float d[4], const float2 a0, const float2 a1,
                                         const float2 bf) {
    asm volatile(
        "mma.sync.aligned.m16n8k8.row.col.f32.tf32.tf32.f32 "
        "{%0,%1,%2,%3}, {%4,%5,%6,%7}, {%8,%9}, {%0,%1,%2,%3};"
        : "+f"(d[0]), "+f"(d[1]), "+f"(d[2]), "+f"(d[3])
        : "r"(__float_as_uint(a0.x)), "r"(__float_as_uint(a1.x)),
          "r"(__float_as_uint(a0.y)), "r"(__float_as_uint(a1.y)),
          "r"(__float_as_uint(bf.x)), "r"(__float_as_uint(bf.y)));
}

// ---------------- MLP layer 0+1 ----------------
__global__ void k_mlp01(const float* __restrict__ xm,
                        const float* __restrict__ w0, const float* __restrict__ b0,
                        const float* __restrict__ w1, const float* __restrict__ b1) {
    int b = blockIdx.x;
    int t = threadIdx.x;
    __shared__ float sm[16];
    __shared__ float sh0[256];
    if (t < 16) sm[t] = xm[b * 16 + t];
    __syncthreads();
    float a = b0[t];
    #pragma unroll
    for (int k = 0; k < 16; k++) a += sm[k] * w0[k * 256 + t];
    sh0[t] = fmaxf(a, 0.f);
    __syncthreads();
    for (int j = t; j < 512; j += 256) {
        float a1 = b1[j];
        for (int k = 0; k < 256; k++) a1 += sh0[k] * w1[k * 512 + j];
        g_h1[b * 512 + j] = fmaxf(a1, 0.f);
    }
}

// ---------------- MLP layer 2 ----------------
__global__ void k_mlp2(const float* __restrict__ w2, const float* __restrict__ b2) {
    __shared__ float sh1[16 * 512];
    int t = threadIdx.x;   // 128
    for (int i = t; i < 16 * 512; i += 128) sh1[i] = g_h1[i];
    __syncthreads();
    int j = blockIdx.x * 128 + t;
    if (j >= TOTAL_W) return;
    float acc[16];
    float bb = b2[j];
    #pragma unroll
    for (int s = 0; s < 16; s++) acc[s] = bb;
    #pragma unroll 4
    for (int k = 0; k < 512; k++) {
        float w = w2[k * TOTAL_W + j];
        #pragma unroll
        for (int s = 0; s < 16; s++) acc[s] += sh1[s * 512 + k] * w;
    }
    #pragma unroll
    for (int s = 0; s < 16; s++) g_flat[s * TOTAL_W + j] = fmaxf(acc[s], 0.f);
}

// ---------------- conv1 weight prep (tf32-rounded fragment layout) ----------------
__global__ void k_wprep() {
    int b = blockIdx.x, s = blockIdx.y;
    int t = threadIdx.x;
    const float* src = g_flat + b * TOTAL_W + OFF_W1;
    for (int i = t; i < 2048; i += 256) {
        int kk = i >> 9;
        int rem = i & 511;
        int jl = rem >> 7;
        int rem2 = rem & 127;
        int oc = rem2 >> 1, jh = rem2 & 1;
        g_wt[b * WT_PER_B + (((s * 4 + kk) * 4 + jl) * WROW_F2 + oc) * 2 + jh] =
            tf32r(src[(oc * 32 + kk * 8 + jh * 4 + jl) * 9 + s]);
    }
}

// ---------------- zero the 1-px guard border of g_c0p ----------------
__global__ void k_zeroborder() {
    int i = blockIdx.x * 256 + threadIdx.x;
    const int NB = 16 * 16 * 1028;
    if (i >= NB) return;
    int bp = i / 1028, r = i - bp * 1028;
    int py, px;
    if (r < 258)      { py = 0;          px = r; }
    else if (r < 516) { py = 257;        px = r - 258; }
    else if (r < 772) { py = r - 516 + 1; px = 0; }
    else              { py = r - 772 + 1; px = 257; }
    g_c0p[(size_t)bp * 66564 + py * 258 + px] = make_float2(0.f, 0.f);
}

// ---------------- conv0: 1 -> 32, pair-interleaved planar padded output ----------------
__global__ void k_conv0(const float* __restrict__ x) {
    int b = blockIdx.z;
    int t = threadIdx.x;
    __shared__ float wsh[288];
    for (int i = t; i < 288; i += 256) wsh[i] = g_flat[b * TOTAL_W + i];
    __syncthreads();
    int px = blockIdx.x * 16 + (t & 15);
    int py = blockIdx.y * 16 + (t >> 4);
    float win[9];
    #pragma unroll
    for (int dy = 0; dy < 3; dy++)
        #pragma unroll
        for (int dx = 0; dx < 3; dx++) {
            int yy = py + dy - 1, xx = px + dx - 1;
            win[dy * 3 + dx] = (yy >= 0 && yy < H && xx >= 0 && xx < W)
                                   ? x[(b * H + yy) * W + xx] : 0.f;
        }
    float v[32];
    #pragma unroll
    for (int oc = 0; oc < 32; oc++) {
        float a = 0.f;
        #pragma unroll
        for (int k = 0; k < 9; k++) a += win[k] * wsh[oc * 9 + k];
        v[oc] = tf32r(a);
    }
    #pragma unroll
    for (int kk = 0; kk < 4; kk++)
        #pragma unroll
        for (int jl = 0; jl < 4; jl++) {
            int plane = kk * 4 + jl;
            g_c0p[((size_t)(b * 16 + plane) * 258 + py + 1) * 258 + px + 1] =
                make_float2(v[kk * 8 + jl], v[kk * 8 + 4 + jl]);
        }
}

// ---------------- conv1: persistent tf32 mma, cp.async double-buffered ----------------
// Block: batch b, 64-px x-strip, 32 rows (8 tiles of 4 rows). 8 warps = 4M x 2N.
// Input smem buffer: 16 planes x 452 f2 (rows pitch 74 f2), conflict-free.
static const int SMW_BYTES = 144 * WROW_F2 * 8;          // 78336
static const int PLANE_F2 = 452;
static const int BUF_BYTES = 16 * PLANE_F2 * 8;          // 57856
static const int CONV1_SMEM = SMW_BYTES + 2 * BUF_BYTES; // 194048

__global__ void __launch_bounds__(256) k_conv1mma() {
    extern __shared__ char smem[];
    float2* smw = (float2*)smem;
    int t = threadIdx.x;
    int b = blockIdx.z;
    int x0 = blockIdx.x * 64;        // gridDim.x = 4
    int ys = blockIdx.y * 32;        // gridDim.y = 8

    // stage weights once per block
    {
        const float4* src = (const float4*)(g_wt + (size_t)b * WT_PER_B);
        float4* dst = (float4*)smw;
        for (int i = t; i < WT_PER_B / 4; i += 256) dst[i] = src[i];
    }
    uint32_t sbase = smem_u32(smem);
    const float2* srcb = g_c0p + (size_t)b * 16 * 66564;

    // stage one 6-row tile (base output row yt) into buffer `bi` via cp.async
    auto stage = [&](int yt, int bi) {
        uint32_t bufaddr = sbase + SMW_BYTES + bi * BUF_BYTES;
        for (int i = t; i < 3168; i += 256) {           // 16 planes * 6 rows * 33 chunks
            int p = i / 198;
            int rem = i - p * 198;
            int r = rem / 33;
            int c = rem - r * 33;
            const float2* src = srcb + (size_t)p * 66564 + (yt + r) * 258 + x0 + c * 2;
            uint32_t dst = bufaddr + (uint32_t)((p * PLANE_F2 + r * 74 + c * 2) * 8);
            asm volatile("cp.async.cg.shared.global [%0], [%1], 16;"
                         :: "r"(dst), "l"(src) : "memory");
        }
        asm volatile("cp.async.commit_group;" ::: "memory");
    };

    int wid = t >> 5, lane = t & 31;
    int wm = wid & 3;            // M slice = output row within tile
    int wn = wid >> 2;           // N slice
    int oc0 = wn * 32;
    int lrow = lane >> 2, lcol = lane & 3;

    stage(ys, 0);                // prologue: tile 0

    for (int ti = 0; ti < 8; ti++) {
        int yt = ys + ti * 4;
        if (ti < 7) {
            stage(yt + 4, (ti + 1) & 1);
            asm volatile("cp.async.wait_group 1;" ::: "memory");
        } else {
            asm volatile("cp.async.wait_group 0;" ::: "memory");
        }
        __syncthreads();

        const float2* smi = (const float2*)(smem + SMW_BYTES + (ti & 1) * BUF_BYTES);

        float d[16][4];
        #pragma unroll
        for (int i = 0; i < 16; i++)
            #pragma unroll
            for (int j = 0; j < 4; j++) d[i][j] = 0.f;

        #pragma unroll
        for (int s = 0; s < 9; s++) {
            int dy = s / 3;
            int dx = s - dy * 3;
            #pragma unroll
            for (int kk = 0; kk < 4; kk++) {
                float2 bf[4];
                const float2* wrow = smw + ((s * 4 + kk) * 4 + lcol) * WROW_F2 + oc0 + lrow;
                #pragma unroll
                for (int ni = 0; ni < 4; ni++) bf[ni] = wrow[ni * 8];
                const float2* arow = smi + (kk * 4 + lcol) * PLANE_F2 + (wm + dy) * 74
                                     + lrow + dx;
                float2 af0[4], af1[4];
                #pragma unroll
                for (int mi = 0; mi < 4; mi++) {
                    af0[mi] = arow[mi * 16];
                    af1[mi] = arow[mi * 16 + 8];
                }
                #pragma unroll
                for (int mi = 0; mi < 4; mi++)
                    #pragma unroll
                    for (int ni = 0; ni < 4; ni++)
                        mma_tf32(d[mi * 4 + ni], af0[mi], af1[mi], bf[ni]);
            }
        }

        // store planar g_c1[b][oc][y][x]
        int yo = yt + wm;
        #pragma unroll
        for (int mi = 0; mi < 4; mi++) {
            int xb = x0 + mi * 16 + lrow;
            #pragma unroll
            for (int ni = 0; ni < 4; ni++) {
                int oc = oc0 + ni * 8 + lcol * 2;
                float* p = &g_c1[(((size_t)b * 64 + oc) * 256 + yo) * 256 + xb];
                p[0] = d[mi * 4 + ni][0];
                p[65536] = d[mi * 4 + ni][1];
                p[8] = d[mi * 4 + ni][2];
                p[65536 + 8] = d[mi * 4 + ni][3];
            }
        }
        __syncthreads();
    }
}

// ---------------- conv2: 64 -> 1 ----------------
__global__ void k_conv2(float* __restrict__ out) {
    int b = blockIdx.z;
    int tx0 = blockIdx.x * 16, ty0 = blockIdx.y * 16;
    __shared__ float s2[16 * 18 * 19];
    __shared__ float w2s[16 * 9];
    int t = threadIdx.x;
    int px = t & 15, py = t >> 4;
    const float* wb = g_flat + b * TOTAL_W + OFF_W2;
    float acc = 0.f;

    for (int cc = 0; cc < 4; cc++) {
        __syncthreads();
        for (int i = t; i < 16 * 324; i += 256) {
            int icl = i / 324;
            int rem = i - icl * 324;
            int r = rem / 18, c = rem - r * 18;
            int y = ty0 + r - 1, xx = tx0 + c - 1;
            int ic = cc * 16 + icl;
            s2[icl * 342 + r * 19 + c] =
                (y >= 0 && y < H && xx >= 0 && xx < W)
                    ? g_c1[(((size_t)b * 64 + ic) * H + y) * W + xx] : 0.f;
        }
        for (int i = t; i < 144; i += 256)
            w2s[i] = wb[cc * 16 * 9 + i];
        __syncthreads();

        for (int icl = 0; icl < 16; icl++) {
            const float* sp = &s2[icl * 342 + py * 19 + px];
            const float* wp = &w2s[icl * 9];
            #pragma unroll
            for (int dy = 0; dy < 3; dy++)
                #pragma unroll
                for (int dx = 0; dx < 3; dx++)
                    acc += sp[dy * 19 + dx] * wp[dy * 3 + dx];
        }
    }
    out[(size_t)b * H * W + (ty0 + py) * W + (tx0 + px)] = acc;
}

// ---------------------------------------------------------------------------
extern "C" void kernel_launch(void* const* d_in, const int* in_sizes, int n_in,
                              void* d_out, int out_size) {
    const float* x_meta = (const float*)d_in[0];
    const float* x      = (const float*)d_in[1];
    const float* w0     = (const float*)d_in[2];
    const float* b0     = (const float*)d_in[3];
    const float* w1     = (const float*)d_in[4];
    const float* b1     = (const float*)d_in[5];
    const float* w2     = (const float*)d_in[6];
    const float* b2     = (const float*)d_in[7];
    float* out = (float*)d_out;

    static int smem_set = 0;
    if (!smem_set) {
        cudaFuncSetAttribute(k_conv1mma, cudaFuncAttributeMaxDynamicSharedMemorySize,
                             CONV1_SMEM);
        smem_set = 1;
    }

    k_mlp01<<<16, 256>>>(x_meta, w0, b0, w1, b1);
    k_mlp2<<<(TOTAL_W + 127) / 128, 128>>>(w2, b2);
    k_wprep<<<dim3(16, 9), 256>>>();
    k_zeroborder<<<(16 * 16 * 1028 + 255) / 256, 256>>>();
    k_conv0<<<dim3(16, 16, 16), 256>>>(x);
    k_conv1mma<<<dim3(4, 8, 16), 256, CONV1_SMEM>>>();
    k_conv2<<<dim3(16, 16, 16), 256>>>(out);
}

// round 6
// speedup vs baseline: 2.0064x; 2.0064x over previous
#include <cuda_runtime.h>
#include <cuda_bf16.h>
#include <cstdint>

// ---------------------------------------------------------------------------
// DynamicModel hypernetwork:
//   MLP(16->256->512->19296, relu all) generates per-sample conv weights
//   conv0: 1->32 3x3 SAME ; conv1: 32->64 (bf16 mma.m16n8k16 + ldmatrix) ;
//   conv2: 64->1.  B=16, H=W=256
// ---------------------------------------------------------------------------

static const int B = 16, H = 256, W = 256;
static const int TOTAL_W = 19296;
static const int OFF_W1 = 288;
static const int OFF_W2 = 18720;

// conv1 weights, ldmatrix-ready: per batch 18 tiles (s*2+kk) of 64 rows,
// each row: 16 bf16 (ic halves) = 32 B payload, 48 B stride (conflict-free).
static const int WTILE_U32 = 768;                 // 64 * 12 u32
static const int WT_PER_B_U32 = 18 * WTILE_U32;   // 13824 u32 = 55296 B

// Scratch
__device__ float g_h1[16 * 512];
__device__ float g_flat[16 * TOTAL_W];
__device__ uint32_t g_wtb[16 * WT_PER_B_U32];
// conv0 out: channel-last bf16, padded 258x258, zero border.
// [b][py][px][16 u32]  (u32 j = bf16x2 of channels 2j, 2j+1)
__device__ uint32_t g_c0h[(size_t)16 * 258 * 258 * 16];
__device__ float g_c1[(size_t)16 * 64 * 256 * 256];      // planar [b][oc][y][x]

// ---------------- helpers ----------------
__device__ __forceinline__ uint32_t bf16pack(float lo, float hi) {
    uint32_t r;
    asm("cvt.rn.bf16x2.f32 %0, %1, %2;" : "=r"(r) : "f"(hi), "f"(lo));
    return r;
}
__device__ __forceinline__ uint32_t smem_u32(const void* p) {
    uint32_t a;
    asm("{ .reg .u64 t; cvta.to.shared.u64 t, %1; cvt.u32.u64 %0, t; }" : "=r"(a) : "l"(p));
    return a;
}
__device__ __forceinline__ void ldmx4(uint32_t* r, uint32_t addr) {
    asm volatile("ldmatrix.sync.aligned.m8n8.x4.shared.b16 {%0,%1,%2,%3}, [%4];"
                 : "=r"(r[0]), "=r"(r[1]), "=r"(r[2]), "=r"(r[3]) : "r"(addr));
}
__device__ __forceinline__ void mma_bf16(float d[4], const uint32_t a[4],
                                         uint32_t b0, uint32_t b1) {
    asm volatile(
        "mma.sync.aligned.m16n8k16.row.col.f32.bf16.bf16.f32 "
        "{%0,%1,%2,%3}, {%4,%5,%6,%7}, {%8,%9}, {%0,%1,%2,%3};"
        : "+f"(d[0]), "+f"(d[1]), "+f"(d[2]), "+f"(d[3])
        : "r"(a[0]), "r"(a[1]), "r"(a[2]), "r"(a[3]), "r"(b0), "r"(b1));
}

// ---------------- MLP layer 0+1 ----------------
__global__ void k_mlp01(const float* __restrict__ xm,
                        const float* __restrict__ w0, const float* __restrict__ b0,
                        const float* __restrict__ w1, const float* __restrict__ b1) {
    int b = blockIdx.x;
    int t = threadIdx.x;
    __shared__ float sm[16];
    __shared__ float sh0[256];
    if (t < 16) sm[t] = xm[b * 16 + t];
    __syncthreads();
    float a = b0[t];
    #pragma unroll
    for (int k = 0; k < 16; k++) a += sm[k] * w0[k * 256 + t];
    sh0[t] = fmaxf(a, 0.f);
    __syncthreads();
    for (int j = t; j < 512; j += 256) {
        float a1 = b1[j];
        for (int k = 0; k < 256; k++) a1 += sh0[k] * w1[k * 512 + j];
        g_h1[b * 512 + j] = fmaxf(a1, 0.f);
    }
}

// ---------------- MLP layer 2 ----------------
__global__ void k_mlp2(const float* __restrict__ w2, const float* __restrict__ b2) {
    __shared__ float sh1[16 * 512];
    int t = threadIdx.x;   // 128
    for (int i = t; i < 16 * 512; i += 128) sh1[i] = g_h1[i];
    __syncthreads();
    int j = blockIdx.x * 128 + t;
    if (j >= TOTAL_W) return;
    float acc[16];
    float bb = b2[j];
    #pragma unroll
    for (int s = 0; s < 16; s++) acc[s] = bb;
    #pragma unroll 4
    for (int k = 0; k < 512; k++) {
        float w = w2[k * TOTAL_W + j];
        #pragma unroll
        for (int s = 0; s < 16; s++) acc[s] += sh1[s * 512 + k] * w;
    }
    #pragma unroll
    for (int s = 0; s < 16; s++) g_flat[s * TOTAL_W + j] = fmaxf(acc[s], 0.f);
}

// ---------------- conv1 weight prep: bf16 ldmatrix tile layout ----------------
__global__ void k_wprep() {
    int b = blockIdx.x;
    int t = threadIdx.x;
    const float* src = g_flat + b * TOTAL_W + OFF_W1;
    // 18 tiles x 64 oc x 8 pairs
    for (int i = t; i < 9216; i += 256) {
        int s2 = i >> 9;                // tile = s*2 + kk
        int rem = i & 511;
        int oc = rem >> 3, j = rem & 7;
        int s = s2 >> 1, kk = s2 & 1;
        int ic = kk * 16 + 2 * j;
        float lo = src[(oc * 32 + ic) * 9 + s];
        float hi = src[(oc * 32 + ic + 1) * 9 + s];
        g_wtb[b * WT_PER_B_U32 + s2 * WTILE_U32 + oc * 12 + j] = bf16pack(lo, hi);
    }
}

// ---------------- zero guard border of g_c0h ----------------
__global__ void k_zeroborder() {
    int i = blockIdx.x * 256 + threadIdx.x;
    const int NB = 16 * 1028 * 4;          // batches x border px x 16B-chunks
    if (i >= NB) return;
    int c = i & 3;
    int r4 = i >> 2;
    int bp = r4 / 1028, r = r4 - bp * 1028;
    int py, px;
    if (r < 258)      { py = 0;           px = r; }
    else if (r < 516) { py = 257;         px = r - 258; }
    else if (r < 772) { py = r - 516 + 1; px = 0; }
    else              { py = r - 772 + 1; px = 257; }
    uint4* dst = (uint4*)(g_c0h + ((size_t)(bp * 258 + py) * 258 + px) * 16);
    dst[c] = make_uint4(0, 0, 0, 0);
}

// ---------------- conv0: 1 -> 32, channel-last bf16 padded output ----------------
__global__ void k_conv0(const float* __restrict__ x) {
    int b = blockIdx.z;
    int t = threadIdx.x;
    __shared__ float wsh[288];
    for (int i = t; i < 288; i += 256) wsh[i] = g_flat[b * TOTAL_W + i];
    __syncthreads();
    int px = blockIdx.x * 16 + (t & 15);
    int py = blockIdx.y * 16 + (t >> 4);
    float win[9];
    #pragma unroll
    for (int dy = 0; dy < 3; dy++)
        #pragma unroll
        for (int dx = 0; dx < 3; dx++) {
            int yy = py + dy - 1, xx = px + dx - 1;
            win[dy * 3 + dx] = (yy >= 0 && yy < H && xx >= 0 && xx < W)
                                   ? x[(b * H + yy) * W + xx] : 0.f;
        }
    uint32_t u[16];
    #pragma unroll
    for (int j = 0; j < 16; j++) {
        float lo = 0.f, hi = 0.f;
        #pragma unroll
        for (int k = 0; k < 9; k++) {
            lo += win[k] * wsh[(2 * j) * 9 + k];
            hi += win[k] * wsh[(2 * j + 1) * 9 + k];
        }
        u[j] = bf16pack(lo, hi);
    }
    uint4* dst = (uint4*)(g_c0h + ((size_t)(b * 258 + py + 1) * 258 + px + 1) * 16);
    #pragma unroll
    for (int c = 0; c < 4; c++)
        dst[c] = make_uint4(u[c * 4], u[c * 4 + 1], u[c * 4 + 2], u[c * 4 + 3]);
}

// ---------------- conv1: bf16 mma + ldmatrix, cp.async double-buffered ----------------
// Block: batch b, 64-px x-strip, 16 rows = 4 tiles of 4 rows. 8 warps = 4M x 2N.
// A smem: 6 rows x pitch 4352 B; pixel x' at x'*64, 16B col c swizzled c^((x'>>1)&3).
// W smem: 18 tiles x 64 rows x 48 B stride.
static const int SMW_BYTES = 18 * 64 * 48;               // 55296
static const int APITCH = 4352;
static const int BUF_BYTES = 6 * APITCH;                 // 26112
static const int CONV1_SMEM = SMW_BYTES + 2 * BUF_BYTES; // 107520

__global__ void __launch_bounds__(256, 2) k_conv1mma() {
    extern __shared__ char smem[];
    int t = threadIdx.x;
    int b = blockIdx.z;
    int x0 = blockIdx.x * 64;        // gridDim.x = 4
    int ys = blockIdx.y * 16;        // gridDim.y = 16

    // stage weights once per block
    {
        const uint4* src = (const uint4*)(g_wtb + (size_t)b * WT_PER_B_U32);
        uint4* dst = (uint4*)smem;
        for (int i = t; i < SMW_BYTES / 16; i += 256) dst[i] = src[i];
    }
    uint32_t sbase = smem_u32(smem);
    const uint32_t* srcb = g_c0h + (size_t)b * 258 * 258 * 16;

    auto stage = [&](int yt, int bi) {
        uint32_t bufaddr = sbase + SMW_BYTES + bi * BUF_BYTES;
        for (int i = t; i < 1584; i += 256) {         // 6 rows * 66 px * 4 chunks
            int c = i & 3;
            int rest = i >> 2;
            int r = rest / 66;
            int xp = rest - r * 66;
            const uint32_t* src = srcb + ((size_t)((yt + r) * 258 + x0 + xp)) * 16 + c * 4;
            uint32_t dst = bufaddr + r * APITCH + xp * 64 + ((c ^ ((xp >> 1) & 3)) << 4);
            asm volatile("cp.async.cg.shared.global [%0], [%1], 16;"
                         :: "r"(dst), "l"(src) : "memory");
        }
        asm volatile("cp.async.commit_group;" ::: "memory");
    };

    int wid = t >> 5, lane = t & 31;
    int wm = wid & 3;                 // M slice = output row within tile
    int wn = wid >> 2;                // N slice
    int oc0 = wn * 32;
    int q = lane >> 3, rl = lane & 7;

    // per-lane precomputed A offsets: ax[kk][dx]
    int xpp = (q & 1) * 8 + rl;       // pixel offset within 16-group
    int cb = q >> 1;                  // 16B column base
    uint32_t ax[2][3];
    #pragma unroll
    for (int kk = 0; kk < 2; kk++)
        #pragma unroll
        for (int dx = 0; dx < 3; dx++) {
            int xp = dx + xpp;
            int c = kk * 2 + cb;
            ax[kk][dx] = xp * 64 + ((c ^ ((xp >> 1) & 3)) << 4);
        }
    // per-lane B offset within a tile
    uint32_t bl_off = (uint32_t)(((q >> 1) * 8 + rl) * 48 + (q & 1) * 16);

    stage(ys, 0);                     // prologue

    for (int ti = 0; ti < 4; ti++) {
        int yt = ys + ti * 4;
        if (ti < 3) {
            stage(yt + 4, (ti + 1) & 1);
            asm volatile("cp.async.wait_group 1;" ::: "memory");
        } else {
            asm volatile("cp.async.wait_group 0;" ::: "memory");
        }
        __syncthreads();

        uint32_t bufaddr = sbase + SMW_BYTES + (ti & 1) * BUF_BYTES;

        float d[16][4];
        #pragma unroll
        for (int i = 0; i < 16; i++)
            #pragma unroll
            for (int j = 0; j < 4; j++) d[i][j] = 0.f;

        #pragma unroll
        for (int s = 0; s < 9; s++) {
            int dy = s / 3;
            int dx = s - dy * 3;
            uint32_t rowbase = bufaddr + (wm + dy) * APITCH;
            #pragma unroll
            for (int kk = 0; kk < 2; kk++) {
                uint32_t bf[8];
                uint32_t baddr = sbase + (s * 2 + kk) * 3072 + bl_off;
                ldmx4(bf, baddr + oc0 * 48);
                ldmx4(bf + 4, baddr + (oc0 + 16) * 48);
                #pragma unroll
                for (int mi = 0; mi < 4; mi++) {
                    uint32_t af[4];
                    ldmx4(af, rowbase + mi * 1024 + ax[kk][dx]);
                    #pragma unroll
                    for (int ni = 0; ni < 4; ni++)
                        mma_bf16(d[mi * 4 + ni], af, bf[2 * ni], bf[2 * ni + 1]);
                }
            }
        }

        // store planar g_c1[b][oc][y][x]
        int yo = yt + wm;
        int r = lane >> 2;
        #pragma unroll
        for (int mi = 0; mi < 4; mi++) {
            int xb = x0 + mi * 16 + r;
            #pragma unroll
            for (int ni = 0; ni < 4; ni++) {
                int oc = oc0 + ni * 8 + (lane & 3) * 2;
                float* p = &g_c1[(((size_t)b * 64 + oc) * 256 + yo) * 256 + xb];
                p[0] = d[mi * 4 + ni][0];
                p[65536] = d[mi * 4 + ni][1];
                p[8] = d[mi * 4 + ni][2];
                p[65536 + 8] = d[mi * 4 + ni][3];
            }
        }
        __syncthreads();
    }
}

// ---------------- conv2: 64 -> 1 ----------------
__global__ void k_conv2(float* __restrict__ out) {
    int b = blockIdx.z;
    int tx0 = blockIdx.x * 16, ty0 = blockIdx.y * 16;
    __shared__ float s2[16 * 18 * 19];
    __shared__ float w2s[16 * 9];
    int t = threadIdx.x;
    int px = t & 15, py = t >> 4;
    const float* wb = g_flat + b * TOTAL_W + OFF_W2;
    float acc = 0.f;

    for (int cc = 0; cc < 4; cc++) {
        __syncthreads();
        for (int i = t; i < 16 * 324; i += 256) {
            int icl = i / 324;
            int rem = i - icl * 324;
            int r = rem / 18, c = rem - r * 18;
            int y = ty0 + r - 1, xx = tx0 + c - 1;
            int ic = cc * 16 + icl;
            s2[icl * 342 + r * 19 + c] =
                (y >= 0 && y < H && xx >= 0 && xx < W)
                    ? g_c1[(((size_t)b * 64 + ic) * H + y) * W + xx] : 0.f;
        }
        for (int i = t; i < 144; i += 256)
            w2s[i] = wb[cc * 16 * 9 + i];
        __syncthreads();

        for (int icl = 0; icl < 16; icl++) {
            const float* sp = &s2[icl * 342 + py * 19 + px];
            const float* wp = &w2s[icl * 9];
            #pragma unroll
            for (int dy = 0; dy < 3; dy++)
                #pragma unroll
                for (int dx = 0; dx < 3; dx++)
                    acc += sp[dy * 19 + dx] * wp[dy * 3 + dx];
        }
    }
    out[(size_t)b * H * W + (ty0 + py) * W + (tx0 + px)] = acc;
}

// ---------------------------------------------------------------------------
extern "C" void kernel_launch(void* const* d_in, const int* in_sizes, int n_in,
                              void* d_out, int out_size) {
    const float* x_meta = (const float*)d_in[0];
    const float* x      = (const float*)d_in[1];
    const float* w0     = (const float*)d_in[2];
    const float* b0     = (const float*)d_in[3];
    const float* w1     = (const float*)d_in[4];
    const float* b1     = (const float*)d_in[5];
    const float* w2     = (const float*)d_in[6];
    const float* b2     = (const float*)d_in[7];
    float* out = (float*)d_out;

    static int smem_set = 0;
    if (!smem_set) {
        cudaFuncSetAttribute(k_conv1mma, cudaFuncAttributeMaxDynamicSharedMemorySize,
                             CONV1_SMEM);
        smem_set = 1;
    }

    k_mlp01<<<16, 256>>>(x_meta, w0, b0, w1, b1);
    k_mlp2<<<(TOTAL_W + 127) / 128, 128>>>(w2, b2);
    k_wprep<<<16, 256>>>();
    k_zeroborder<<<(16 * 1028 * 4 + 255) / 256, 256>>>();
    k_conv0<<<dim3(16, 16, 16), 256>>>(x);
    k_conv1mma<<<dim3(4, 16, 16), 256, CONV1_SMEM>>>();
    k_conv2<<<dim3(16, 16, 16), 256>>>(out);
}